// round 8
// baseline (speedup 1.0000x reference)
#include <cuda_runtime.h>
#include <math.h>

#define B 64
#define N 8192
#define M 128
#define EPS 1e-16f
#define EPS_COS 1e-8f

// ---------------- scratch (no allocation allowed) ----------------
__device__ float g_cos[B * N];            // 2 MB: cos, then reused as addr scratch
__device__ float g_w[B * N];              // 2 MB: final weights
__device__ float g_pr[B * 128 * M];       // 4 MB: partial r [B][128][M]
__device__ unsigned int g_cnt_c[B];       // cos-completion tickets
__device__ unsigned int g_cnt_w[B];       // write-completion tickets
__device__ unsigned int g_flag[B];        // per-batch "w ready" flags

#define CROWS 64          // memory rows per cos block
#define NBLK_COS (N / CROWS)              // 128 cos blocks per batch
#define GRID_COS (B * NBLK_COS)           // 8192
#define ROWS_PER_BLK 64   // memory rows per write block
#define GRID_TOT (GRID_COS + B * (N / ROWS_PER_BLK))  // 16384

__global__ __launch_bounds__(256) void mega_kernel(
    const float* __restrict__ mem, const float* __restrict__ k,
    const float* __restrict__ beta, const float* __restrict__ g,
    const float* __restrict__ s, const float* __restrict__ gamma,
    const float* __restrict__ w_prev, const float* __restrict__ e,
    const float* __restrict__ a, float* __restrict__ newmem,
    float* __restrict__ r_out)
{
    __shared__ union {
        struct { float4 ks[32]; float invnk; } c;
        struct { float4 sd[256]; } w;
    } sh;
    __shared__ float red[8];
    __shared__ bool is_last;

    int bid = blockIdx.x;
    int tid = threadIdx.x;
    int warp = tid >> 5, lane = tid & 31;

    if (bid < GRID_COS) {
        // ================= cos phase =================
        int b = bid >> 7;               // / NBLK_COS
        int blk = bid & (NBLK_COS - 1);

        if (tid < 32) {
            float4 k4 = reinterpret_cast<const float4*>(k + b * M)[tid];
            k4.x += EPS; k4.y += EPS; k4.z += EPS; k4.w += EPS;
            sh.c.ks[tid] = k4;
            float nk2 = k4.x * k4.x + k4.y * k4.y + k4.z * k4.z + k4.w * k4.w;
            #pragma unroll
            for (int t = 16; t > 0; t >>= 1)
                nk2 += __shfl_xor_sync(0xffffffffu, nk2, t);
            if (tid == 0) sh.c.invnk = 1.f / fmaxf(sqrtf(nk2), EPS_COS);
        }
        __syncthreads();

        int sub = lane >> 3, lane8 = lane & 7;   // 4 row-groups of 8 lanes
        int n0 = blk * CROWS;
        float invnk = sh.c.invnk;

        #pragma unroll
        for (int iter = 0; iter < 2; ++iter) {
            int row = n0 + iter * 32 + warp * 4 + sub;
            const float4* mp = reinterpret_cast<const float4*>(
                mem + ((size_t)b * N + row) * M);

            float dot = 0.f, nm2 = 0.f;
            #pragma unroll
            for (int j = 0; j < 4; ++j) {
                float4 m4 = __ldcs(mp + lane8 + j * 8);
                float4 k4 = sh.c.ks[lane8 + j * 8];
                float mx = m4.x + EPS, my = m4.y + EPS,
                      mz = m4.z + EPS, mw = m4.w + EPS;
                dot += mx * k4.x + my * k4.y + mz * k4.z + mw * k4.w;
                nm2 += mx * mx + my * my + mz * mz + mw * mw;
            }
            #pragma unroll
            for (int t = 4; t > 0; t >>= 1) {
                dot += __shfl_xor_sync(0xffffffffu, dot, t);
                nm2 += __shfl_xor_sync(0xffffffffu, nm2, t);
            }
            if (lane8 == 0) {
                float nm = fmaxf(sqrtf(nm2), EPS_COS);
                g_cos[(size_t)b * N + row] = dot * invnk / nm;
            }
        }

        // ---- ticket: last cos block of this batch runs addr phase ----
        __threadfence();
        if (tid == 0) {
            unsigned int v = atomicAdd(&g_cnt_c[b], 1u);
            is_last = (v == NBLK_COS - 1u);
            if (is_last) g_cnt_c[b] = 0;   // self-reset for graph replay
        }
        __syncthreads();
        if (!is_last) return;

        // ================= addr phase (in-place in g_cos, L2-hot) =========
        float betav = beta[b], gv = g[b], gammav = gamma[b];
        float s0 = s[b * 3 + 0], s1 = s[b * 3 + 1], s2 = s[b * 3 + 2];
        float* cw = g_cos + (size_t)b * N;
        float* wo = g_w + (size_t)b * N;
        const float* wpv = w_prev + (size_t)b * N;

        // pass 1: ev = exp(beta*cos) (|beta*cos| <= 5, no max needed), sum
        float sum = 0.f;
        #pragma unroll
        for (int j = 0; j < N / 256; ++j) {
            int i = tid + j * 256;
            float ev = __expf(betav * cw[i]);
            cw[i] = ev;
            sum += ev;
        }
        #pragma unroll
        for (int t = 16; t > 0; t >>= 1)
            sum += __shfl_xor_sync(0xffffffffu, sum, t);
        if (lane == 0) red[warp] = sum;
        __syncthreads();
        float bsum = 0.f;
        #pragma unroll
        for (int ww = 0; ww < 8; ++ww) bsum += red[ww];
        float inv = 1.f / bsum;

        // pass 2: wg = g*wc + (1-g)*w_prev (in place)
        #pragma unroll
        for (int j = 0; j < N / 256; ++j) {
            int i = tid + j * 256;
            cw[i] = gv * (cw[i] * inv) + (1.f - gv) * wpv[i];
        }
        __syncthreads();

        // pass 3: shift + sharpen -> g_w, sum
        float sum2 = 0.f;
        #pragma unroll
        for (int j = 0; j < N / 256; ++j) {
            int i = tid + j * 256;
            int im1 = (i == 0) ? (N - 1) : (i - 1);
            int ip1 = (i == N - 1) ? 0 : (i + 1);
            float wh = s0 * cw[im1] + s1 * cw[i] + s2 * cw[ip1];
            float ww = __expf(gammav * __logf(wh));   // wh > 0 always
            wo[i] = ww;
            sum2 += ww;
        }
        #pragma unroll
        for (int t = 16; t > 0; t >>= 1)
            sum2 += __shfl_xor_sync(0xffffffffu, sum2, t);
        __syncthreads();
        if (lane == 0) red[warp] = sum2;
        __syncthreads();
        float bsum2 = 0.f;
        #pragma unroll
        for (int ww = 0; ww < 8; ++ww) bsum2 += red[ww];
        float inv2 = 1.f / (bsum2 + EPS);

        // pass 4: scale
        #pragma unroll
        for (int j = 0; j < N / 256; ++j) {
            int i = tid + j * 256;
            wo[i] *= inv2;
        }

        // publish
        __threadfence();
        if (tid == 0) atomicExch(&g_flag[b], 1u);
        return;
    }

    // ================= write phase =================
    {
        int wb = bid - GRID_COS;
        int b = wb >> 7;                // / 128
        int blk = wb & 127;
        int m4 = tid & 31;              // float4 index along M
        int grp = tid >> 5;             // 8 row groups

        // wait for this batch's weights (producers have lower bids -> safe)
        if (tid == 0) {
            while (atomicAdd(&g_flag[b], 0u) == 0u) __nanosleep(128);
        }
        __syncthreads();

        const float4 e4 = reinterpret_cast<const float4*>(e + b * M)[m4];
        const float4 a4 = reinterpret_cast<const float4*>(a + b * M)[m4];

        int n0 = blk * ROWS_PER_BLK;
        size_t base = ((size_t)b * N + n0) * M;
        const float4* mp = reinterpret_cast<const float4*>(mem + base);
        float4* op = reinterpret_cast<float4*>(newmem + base);
        const float* wp = g_w + (size_t)b * N + n0;

        float4 racc = make_float4(0.f, 0.f, 0.f, 0.f);
        #pragma unroll
        for (int it = 0; it < ROWS_PER_BLK / 8; ++it) {
            int row = it * 8 + grp;
            float wv = __ldg(wp + row);
            float4 mv = __ldcs(mp + row * 32 + m4);
            float4 o;
            o.x = mv.x * (1.f - wv * e4.x) + wv * a4.x;
            o.y = mv.y * (1.f - wv * e4.y) + wv * a4.y;
            o.z = mv.z * (1.f - wv * e4.z) + wv * a4.z;
            o.w = mv.w * (1.f - wv * e4.w) + wv * a4.w;
            __stcs(op + row * 32 + m4, o);
            racc.x += wv * mv.x;
            racc.y += wv * mv.y;
            racc.z += wv * mv.z;
            racc.w += wv * mv.w;
        }

        sh.w.sd[tid] = racc;
        __syncthreads();
        #pragma unroll
        for (int st = 4; st > 0; st >>= 1) {
            if (grp < st) {
                float4 o = sh.w.sd[tid + st * 32];
                sh.w.sd[tid].x += o.x; sh.w.sd[tid].y += o.y;
                sh.w.sd[tid].z += o.z; sh.w.sd[tid].w += o.w;
            }
            __syncthreads();
        }
        if (grp == 0) {
            reinterpret_cast<float4*>(
                g_pr + ((size_t)b * 128 + blk) * M)[m4] = sh.w.sd[tid];
        }

        // ticket: last write block of this batch reduces the partials
        __threadfence();
        if (tid == 0) {
            unsigned int v = atomicAdd(&g_cnt_w[b], 1u);
            is_last = (v == 127u);
            if (is_last) g_cnt_w[b] = 0;   // self-reset
        }
        __syncthreads();
        if (!is_last) return;

        float4 acc = make_float4(0.f, 0.f, 0.f, 0.f);
        const float4* pp = reinterpret_cast<const float4*>(
            g_pr + (size_t)b * 128 * M);
        #pragma unroll
        for (int j = 0; j < 16; ++j) {
            float4 v = pp[(grp + j * 8) * 32 + m4];
            acc.x += v.x; acc.y += v.y; acc.z += v.z; acc.w += v.w;
        }
        __syncthreads();
        sh.w.sd[tid] = acc;
        __syncthreads();
        #pragma unroll
        for (int st = 4; st > 0; st >>= 1) {
            if (grp < st) {
                float4 o = sh.w.sd[tid + st * 32];
                sh.w.sd[tid].x += o.x; sh.w.sd[tid].y += o.y;
                sh.w.sd[tid].z += o.z; sh.w.sd[tid].w += o.w;
            }
            __syncthreads();
        }
        if (grp == 0) {
            reinterpret_cast<float4*>(r_out + b * M)[m4] = sh.w.sd[tid];
        }
        // reset flag for next graph replay (all consumers already passed it)
        if (tid == 0) atomicExch(&g_flag[b], 0u);
    }
}

// ---------------- launch ----------------
extern "C" void kernel_launch(void* const* d_in, const int* in_sizes, int n_in,
                              void* d_out, int out_size) {
    const float* memory = (const float*)d_in[0];
    const float* k      = (const float*)d_in[1];
    const float* beta   = (const float*)d_in[2];
    const float* g      = (const float*)d_in[3];
    const float* s      = (const float*)d_in[4];
    const float* gamma  = (const float*)d_in[5];
    const float* w_prev = (const float*)d_in[6];
    const float* e      = (const float*)d_in[7];
    const float* a      = (const float*)d_in[8];

    float* r_out  = (float*)d_out;            // [B, M]
    float* nm_out = (float*)d_out + B * M;    // [B, N, M]

    mega_kernel<<<GRID_TOT, 256>>>(memory, k, beta, g, s, gamma,
                                   w_prev, e, a, nm_out, r_out);
}